// round 1
// baseline (speedup 1.0000x reference)
#include <cuda_runtime.h>

// ---------------------------------------------------------------------------
// Problem constants
// B=16, N=7, Lq=256, Lp=512, D=768, S=12, Wq=200, Wp=400
// word slots: q 16*200=3200, p 16*400=6400, n 112*400=44800  -> 54400 total
// out layout (floats): q_pooled[0,12288) p_pooled[12288,24576)
//                      q_logits[24576,62976) p_logits[62976,139776)
//                      n_pooled[139776,225792)
// ---------------------------------------------------------------------------
#define TOTAL_WORDS 54400
#define OFF_QPOOL 0
#define OFF_PPOOL 12288
#define OFF_QLOG  24576
#define OFF_PLOG  62976
#define OFF_NPOOL 139776

__device__ float g_logitsum[TOTAL_WORDS * 12];
__device__ float g_count[TOTAL_WORDS];
__device__ float g_coef[TOTAL_WORDS];

typedef unsigned long long u64;

__device__ __forceinline__ u64 pack2(float x) {
    u64 r; asm("mov.b64 %0, {%1, %1};" : "=l"(r) : "f"(x)); return r;
}
__device__ __forceinline__ u64 pack2(float lo, float hi) {
    u64 r; asm("mov.b64 %0, {%1, %2};" : "=l"(r) : "f"(lo), "f"(hi)); return r;
}
__device__ __forceinline__ void fma2(u64& a, u64 x, u64 y) {
    asm("fma.rn.f32x2 %0, %1, %2, %0;" : "+l"(a) : "l"(x), "l"(y));
}
__device__ __forceinline__ u64 add2(u64 x, u64 y) {
    u64 r; asm("add.rn.f32x2 %0, %1, %2;" : "=l"(r) : "l"(x), "l"(y)); return r;
}
__device__ __forceinline__ float2 unpack2(u64 v) {
    float2 r; asm("mov.b64 {%0, %1}, %2;" : "=f"(r.x), "=f"(r.y) : "l"(v)); return r;
}

// ---------------------------------------------------------------------------
// Kernel A: token projection (h[768] @ proj_w[768x12]) + segment-sum into
// g_logitsum / g_count. One warp handles 32 tokens per "pass":
//   lane&3  = d-sublane (covers d = sub*4 + 16*i + k)
//   lane>>2 = token group (8 groups), 4 sequential tokens per group (tt)
// Weights live in smem as f32x2 pairs, row pitch 7 (conflict-free broadcast).
// Total passes: q 128, p 256, n 1792 -> 2176.
// ---------------------------------------------------------------------------
#define WPITCH 7
#define NPASS_TOTAL 2176

__global__ __launch_bounds__(128) void kA(
    const float* __restrict__ qh, const float* __restrict__ ph, const float* __restrict__ nh,
    const int* __restrict__ qw, const int* __restrict__ pw, const int* __restrict__ nwid,
    const float* __restrict__ projw)
{
    __shared__ u64 sw[768 * WPITCH];  // 43008 bytes
    for (int idx = threadIdx.x; idx < 768 * 6; idx += blockDim.x) {
        int d = idx / 6, j = idx % 6;
        sw[d * WPITCH + j] = pack2(projw[d * 12 + 2 * j], projw[d * 12 + 2 * j + 1]);
    }
    __syncthreads();

    const int lane = threadIdx.x & 31;
    const int sub  = lane & 3;
    const int grp  = lane >> 2;
    const int gw   = (blockIdx.x * blockDim.x + threadIdx.x) >> 5;
    const int nwarps = (gridDim.x * blockDim.x) >> 5;
    const u64* swl = sw + sub * 4 * WPITCH;

    for (int p = gw; p < NPASS_TOTAL; p += nwarps) {
        const float* hid; const int* wid; int L, W, wb, lp;
        if (p < 128)      { hid = qh; wid = qw;   L = 256; W = 200; wb = 0;    lp = p; }
        else if (p < 384) { hid = ph; wid = pw;   L = 512; W = 400; wb = 3200; lp = p - 128; }
        else              { hid = nh; wid = nwid; L = 512; W = 400; wb = 9600; lp = p - 384; }

        const int tokBase = lp << 5;           // 32 tokens per pass, L%32==0 so same m
        const int m = tokBase / L;
        const float* hb = hid + (size_t)tokBase * 768 + sub * 4;

        u64 acc[4][6];
        #pragma unroll
        for (int tt = 0; tt < 4; tt++)
            #pragma unroll
            for (int j = 0; j < 6; j++) acc[tt][j] = 0ull;

        #pragma unroll 2
        for (int i = 0; i < 48; i++) {
            float ha[4][4];
            #pragma unroll
            for (int tt = 0; tt < 4; tt++) {
                float4 v = *(const float4*)(hb + (size_t)(grp + 8 * tt) * 768 + i * 16);
                ha[tt][0] = v.x; ha[tt][1] = v.y; ha[tt][2] = v.z; ha[tt][3] = v.w;
            }
            const u64* wrow = swl + i * 16 * WPITCH;
            #pragma unroll
            for (int k = 0; k < 4; k++) {
                u64 w0 = wrow[k * WPITCH + 0];
                u64 w1 = wrow[k * WPITCH + 1];
                u64 w2 = wrow[k * WPITCH + 2];
                u64 w3 = wrow[k * WPITCH + 3];
                u64 w4 = wrow[k * WPITCH + 4];
                u64 w5 = wrow[k * WPITCH + 5];
                #pragma unroll
                for (int tt = 0; tt < 4; tt++) {
                    u64 h2 = pack2(ha[tt][k]);
                    fma2(acc[tt][0], h2, w0);
                    fma2(acc[tt][1], h2, w1);
                    fma2(acc[tt][2], h2, w2);
                    fma2(acc[tt][3], h2, w3);
                    fma2(acc[tt][4], h2, w4);
                    fma2(acc[tt][5], h2, w5);
                }
            }
        }

        // reduce over the 4 d-sublanes (xor 1, xor 2 stay within the group)
        #pragma unroll
        for (int tt = 0; tt < 4; tt++)
            #pragma unroll
            for (int j = 0; j < 6; j++) {
                u64 v = acc[tt][j];
                v = add2(v, __shfl_xor_sync(0xffffffffu, v, 1));
                v = add2(v, __shfl_xor_sync(0xffffffffu, v, 2));
                acc[tt][j] = v;
            }

        if (sub == 0) {
            #pragma unroll
            for (int tt = 0; tt < 4; tt++) {
                int tok = tokBase + grp + 8 * tt;
                int w = wid[tok];
                size_t widx = (size_t)wb + (size_t)m * W + w;
                float* ls = g_logitsum + widx * 12;
                #pragma unroll
                for (int j = 0; j < 6; j++) {
                    float2 f = unpack2(acc[tt][j]);
                    atomicAdd(ls + 2 * j,     f.x);
                    atomicAdd(ls + 2 * j + 1, f.y);
                }
                atomicAdd(g_count + widx, 1.0f);
            }
        }
    }
}

// ---------------------------------------------------------------------------
// Kernel B: per sample — per-word scope softmax -> importance, masked softmax
// over words -> coefficient weight/count; writes q/p logits outputs.
// 144 blocks (16 q, 16 p, 112 n), 128 threads.
// ---------------------------------------------------------------------------
__global__ __launch_bounds__(128) void kB(const float* __restrict__ projb,
                                          const float* __restrict__ simp,
                                          float* __restrict__ out)
{
    const int blk = blockIdx.x;
    int W, wb; float* lout = nullptr;
    if (blk < 16)      { W = 200; wb = blk * 200;              lout = out + OFF_QLOG + blk * 200 * 12; }
    else if (blk < 32) { int m = blk - 16; W = 400; wb = 3200 + m * 400; lout = out + OFF_PLOG + m * 400 * 12; }
    else               { int m = blk - 32; W = 400; wb = 9600 + m * 400; }

    __shared__ float impbuf[400];
    __shared__ float red[4];
    const int tid = threadIdx.x;

    float b[12], si[12];
    #pragma unroll
    for (int s = 0; s < 12; s++) { b[s] = projb[s]; si[s] = simp[s]; }

    for (int w = tid; w < W; w += 128) {
        float c = g_count[wb + w];
        float imp;
        if (c > 0.f) {
            float l[12], mx = -1e30f;
            float invc = 1.f / c;
            #pragma unroll
            for (int s = 0; s < 12; s++) {
                l[s] = g_logitsum[(size_t)(wb + w) * 12 + s] * invc + b[s];
                mx = fmaxf(mx, l[s]);
            }
            float se = 0.f, ai = 0.f;
            #pragma unroll
            for (int s = 0; s < 12; s++) {
                float e = __expf(l[s] - mx);
                se += e; ai += e * si[s];
            }
            imp = ai / se;
            if (lout) {
                #pragma unroll
                for (int s = 0; s < 12; s++) lout[w * 12 + s] = l[s];
            }
        } else {
            imp = -1e4f;
            if (lout) {
                #pragma unroll
                for (int s = 0; s < 12; s++) lout[w * 12 + s] = 0.f;
            }
        }
        impbuf[w] = imp;
    }
    __syncthreads();

    // block max over W
    float mx = -1e30f;
    for (int w = tid; w < W; w += 128) mx = fmaxf(mx, impbuf[w]);
    #pragma unroll
    for (int o = 16; o; o >>= 1) mx = fmaxf(mx, __shfl_xor_sync(0xffffffffu, mx, o));
    if ((tid & 31) == 0) red[tid >> 5] = mx;
    __syncthreads();
    mx = fmaxf(fmaxf(red[0], red[1]), fmaxf(red[2], red[3]));
    __syncthreads();

    // block sum of exp
    float se = 0.f;
    for (int w = tid; w < W; w += 128) se += __expf(impbuf[w] - mx);
    #pragma unroll
    for (int o = 16; o; o >>= 1) se += __shfl_xor_sync(0xffffffffu, se, o);
    if ((tid & 31) == 0) red[tid >> 5] = se;
    __syncthreads();
    se = red[0] + red[1] + red[2] + red[3];
    const float inv = 1.f / se;

    for (int w = tid; w < W; w += 128) {
        float c = g_count[wb + w];
        g_coef[wb + w] = (c > 0.f) ? (__expf(impbuf[w] - mx) * inv) / c : 0.f;
    }
}

// ---------------------------------------------------------------------------
// Kernel C: pooled[m,:] = sum over tokens coef[m, wid] * h[m, tok, :]
// One block = (sample, 64-token slab), 192 threads, float4 per thread (768).
// Blocks: q 16*4=64, p 16*8=128, n 112*8=896 -> 1088. Atomic accumulation.
// ---------------------------------------------------------------------------
__global__ __launch_bounds__(192) void kC(
    const float* __restrict__ qh, const float* __restrict__ ph, const float* __restrict__ nh,
    const int* __restrict__ qw, const int* __restrict__ pw, const int* __restrict__ nwid,
    float* __restrict__ out)
{
    const int blk = blockIdx.x;
    const float* hid; const int* wid; int L, wb, m, slab; float* po;
    if (blk < 64)       { m = blk >> 2;  slab = blk & 3; hid = qh; wid = qw;   L = 256; wb = m * 200;        po = out + OFF_QPOOL + m * 768; }
    else if (blk < 192) { int b2 = blk - 64;  m = b2 >> 3; slab = b2 & 7; hid = ph; wid = pw;   L = 512; wb = 3200 + m * 400; po = out + OFF_PPOOL + m * 768; }
    else                { int b2 = blk - 192; m = b2 >> 3; slab = b2 & 7; hid = nh; wid = nwid; L = 512; wb = 9600 + m * 400; po = out + OFF_NPOOL + m * 768; }

    __shared__ float cf[64];
    const int tid = threadIdx.x;
    const int t0 = slab * 64;
    if (tid < 64) cf[tid] = g_coef[wb + wid[m * L + t0 + tid]];
    __syncthreads();

    const float* hp = hid + (size_t)(m * L + t0) * 768 + tid * 4;
    float ax = 0.f, ay = 0.f, az = 0.f, aw = 0.f;
    #pragma unroll 8
    for (int t = 0; t < 64; t++) {
        float c = cf[t];
        float4 v = *(const float4*)(hp + (size_t)t * 768);
        ax += c * v.x; ay += c * v.y; az += c * v.z; aw += c * v.w;
    }
    float* o = po + tid * 4;
    atomicAdd(o + 0, ax);
    atomicAdd(o + 1, ay);
    atomicAdd(o + 2, az);
    atomicAdd(o + 3, aw);
}

// ---------------------------------------------------------------------------
extern "C" void kernel_launch(void* const* d_in, const int* in_sizes, int n_in,
                              void* d_out, int out_size)
{
    const float* qh    = (const float*)d_in[0];
    const float* ph    = (const float*)d_in[1];
    const float* nh    = (const float*)d_in[2];
    const float* projw = (const float*)d_in[3];
    const float* projb = (const float*)d_in[4];
    const float* simp  = (const float*)d_in[5];
    const int*   qw    = (const int*)d_in[6];
    const int*   pw    = (const int*)d_in[7];
    const int*   nwid  = (const int*)d_in[8];
    float* out = (float*)d_out;

    void* pls = nullptr; cudaGetSymbolAddress(&pls, g_logitsum);
    void* pc  = nullptr; cudaGetSymbolAddress(&pc,  g_count);
    cudaMemsetAsync(pls, 0, sizeof(float) * TOTAL_WORDS * 12);
    cudaMemsetAsync(pc,  0, sizeof(float) * TOTAL_WORDS);
    cudaMemsetAsync(out + OFF_QPOOL, 0, sizeof(float) * 24576);   // q_pooled + p_pooled
    cudaMemsetAsync(out + OFF_NPOOL, 0, sizeof(float) * 86016);   // n_pooled

    kA<<<544, 128>>>(qh, ph, nh, qw, pw, nwid, projw);
    kB<<<144, 128>>>(projb, simp, out);
    kC<<<1088, 192>>>(qh, ph, nh, qw, pw, nwid, out);
}